// round 1
// baseline (speedup 1.0000x reference)
#include <cuda_runtime.h>
#include <cuda_bf16.h>

#define F_DIM 2048
#define B_DIM 2
#define H_DIM 1024
#define N_HEADS 16
#define E_DIM 64
#define FB (F_DIM * B_DIM)   /* 4096 */
#define H3 (3 * H_DIM)       /* 3072 */

// Scratch (device globals: allocation-free per harness rules)
__device__ float g_qkv[FB * H3];                         // 50.3 MB
__device__ float g_ctx[FB * H_DIM];                      // 16.8 MB
__device__ unsigned char g_mask[B_DIM * F_DIM * F_DIM];  // 8.4 MB
__device__ int g_mask_mode;                              // 0=u8, 1=i32, 2=f32

// ---------------------------------------------------------------------------
// Mask dtype detection: jax bool may be serialized as u8, int32 or f32.
// Deterministic byte-pattern probe over the first 4096 elements.
// ---------------------------------------------------------------------------
__global__ void detect_mask_kernel(const unsigned char* __restrict__ m) {
    __shared__ int bad_f32, bad_i32;
    int tid = threadIdx.x;
    if (tid == 0) { bad_f32 = 0; bad_i32 = 0; }
    __syncthreads();
    const float* mf = (const float*)m;
    const int* mi = (const int*)m;
    int lf = 0, li = 0;
    for (int i = tid; i < 4096; i += blockDim.x) {
        float fv = mf[i];
        if (!(fv == 0.0f || fv == 1.0f)) lf = 1;
        int iv = mi[i];
        if (!(iv == 0 || iv == 1)) li = 1;
    }
    if (lf) atomicOr(&bad_f32, 1);
    if (li) atomicOr(&bad_i32, 1);
    __syncthreads();
    if (tid == 0) g_mask_mode = (!bad_f32) ? 2 : ((!bad_i32) ? 1 : 0);
}

__global__ void convert_mask_kernel(const unsigned char* __restrict__ m) {
    long long idx = (long long)blockIdx.x * blockDim.x + threadIdx.x;
    const long long total = (long long)B_DIM * F_DIM * F_DIM;
    if (idx >= total) return;
    int mode = g_mask_mode;
    unsigned char v;
    if (mode == 2)      v = (((const float*)m)[idx] != 0.0f);
    else if (mode == 1) v = (((const int*)m)[idx] != 0);
    else                v = (m[idx] != 0);
    g_mask[idx] = v;
}

// ---------------------------------------------------------------------------
// Tiled SGEMM: C[M,Nc] = A[M,K] @ B[K,Nc] (+ bias over Nc).
// BM=BN=128, BK=8, 256 threads, 8x8 microtile.
// All dims here are multiples of the tile sizes -> no bounds checks.
// ---------------------------------------------------------------------------
__global__ void __launch_bounds__(256, 2)
sgemm_kernel(const float* __restrict__ A, const float* __restrict__ B,
             const float* __restrict__ bias, float* __restrict__ C,
             int M, int Nc, int K) {
    __shared__ float As[8][128];   // stored transposed: As[k][m]
    __shared__ float Bs[8][128];

    int tid = threadIdx.x;
    int tx = tid & 15, ty = tid >> 4;
    int bm = blockIdx.y * 128, bn = blockIdx.x * 128;

    float acc[8][8];
#pragma unroll
    for (int i = 0; i < 8; i++)
#pragma unroll
        for (int j = 0; j < 8; j++) acc[i][j] = 0.0f;

    int arow = tid >> 1, acol = (tid & 1) * 4;
    int brow = tid >> 5, bcol = (tid & 31) * 4;
    const float* Aptr = A + (long long)(bm + arow) * K + acol;
    const float* Bptr = B + (long long)brow * Nc + bn + bcol;

    for (int k0 = 0; k0 < K; k0 += 8) {
        float4 av = *(const float4*)(Aptr + k0);
        float4 bv = *(const float4*)(Bptr + (long long)k0 * Nc);
        As[acol + 0][arow] = av.x;
        As[acol + 1][arow] = av.y;
        As[acol + 2][arow] = av.z;
        As[acol + 3][arow] = av.w;
        *(float4*)&Bs[brow][bcol] = bv;
        __syncthreads();
#pragma unroll
        for (int kk = 0; kk < 8; kk++) {
            float4 a0 = *(const float4*)&As[kk][ty * 8];
            float4 a1 = *(const float4*)&As[kk][ty * 8 + 4];
            float4 b0 = *(const float4*)&Bs[kk][tx * 8];
            float4 b1 = *(const float4*)&Bs[kk][tx * 8 + 4];
            float a[8] = {a0.x, a0.y, a0.z, a0.w, a1.x, a1.y, a1.z, a1.w};
            float b[8] = {b0.x, b0.y, b0.z, b0.w, b1.x, b1.y, b1.z, b1.w};
#pragma unroll
            for (int i = 0; i < 8; i++)
#pragma unroll
                for (int j = 0; j < 8; j++) acc[i][j] += a[i] * b[j];
        }
        __syncthreads();
    }

#pragma unroll
    for (int i = 0; i < 8; i++) {
        int row = bm + ty * 8 + i;
        float* Cp = C + (long long)row * Nc + bn + tx * 8;
#pragma unroll
        for (int j = 0; j < 8; j++) {
            float v = acc[i][j];
            if (bias) v += bias[bn + tx * 8 + j];
            Cp[j] = v;
        }
    }
}

// ---------------------------------------------------------------------------
// Fused flash-style attention.
// qkv layout: [F][B][3H]; per (f,b,n) head slice at n*192: q[0:64], k[64:128], v[128:192].
// Block = (f-tile of 64) x head x batch. 256 threads (16x16), 4x4 microtile.
// smem: Qs[64][64], Ks[64][65] (reused for P), Vs[64][64] = 49408 B dynamic.
// ---------------------------------------------------------------------------
#define ATT_SMEM_FLOATS (64 * 64 + 64 * 65 + 64 * 64)
#define ATT_SMEM_BYTES (ATT_SMEM_FLOATS * 4)

__global__ void __launch_bounds__(256)
attention_kernel(const float* __restrict__ qkv, float* __restrict__ ctx) {
    extern __shared__ float sm[];
    float* Qs = sm;                  // [64][64]
    float* Ks = sm + 64 * 64;        // [64][65]  (also holds P)
    float* Vs = Ks + 64 * 65;        // [64][64]

    int tid = threadIdx.x;
    int tx = tid & 15, ty = tid >> 4;
    int f0 = blockIdx.x * 64;
    int n = blockIdx.y;
    int b = blockIdx.z;

    const long long rowstride = (long long)B_DIM * H3;
    const float* qbase = qkv + (long long)b * H3 + n * (3 * E_DIM);

    // Load Q tile
    for (int i = tid; i < 64 * 64; i += 256) {
        int r = i >> 6, e = i & 63;
        Qs[r * 64 + e] = qbase[(long long)(f0 + r) * rowstride + e];
    }

    float m_i[4], l_i[4], o[4][4];
#pragma unroll
    for (int i = 0; i < 4; i++) {
        m_i[i] = -1e30f;
        l_i[i] = 0.0f;
#pragma unroll
        for (int k = 0; k < 4; k++) o[i][k] = 0.0f;
    }

    const unsigned char* mrow = g_mask + (long long)b * F_DIM * F_DIM;
    const float scale = 0.125f;  // 1/sqrt(64)

    for (int t0 = 0; t0 < F_DIM; t0 += 64) {
        __syncthreads();  // previous-iter readers of Ks(P)/Vs done
        for (int i = tid; i < 64 * 64; i += 256) {
            int r = i >> 6, e = i & 63;
            const float* kb = qbase + (long long)(t0 + r) * rowstride + E_DIM;
            Ks[r * 65 + e] = kb[e];
            Vs[r * 64 + e] = kb[E_DIM + e];
        }
        __syncthreads();

        // S = Q @ K^T for this tile
        float s[4][4];
#pragma unroll
        for (int i = 0; i < 4; i++)
#pragma unroll
            for (int j = 0; j < 4; j++) s[i][j] = 0.0f;
#pragma unroll
        for (int e = 0; e < 64; e++) {
            float qv[4], kv[4];
#pragma unroll
            for (int i = 0; i < 4; i++) qv[i] = Qs[(ty * 4 + i) * 64 + e];
#pragma unroll
            for (int j = 0; j < 4; j++) kv[j] = Ks[(tx * 4 + j) * 65 + e];
#pragma unroll
            for (int i = 0; i < 4; i++)
#pragma unroll
                for (int j = 0; j < 4; j++) s[i][j] += qv[i] * kv[j];
        }

        // scale then mask (matches ref: logits*scale, then where(mask, ., -1e4))
#pragma unroll
        for (int i = 0; i < 4; i++) {
            int fg = f0 + ty * 4 + i;
            const unsigned char* mr = mrow + (long long)fg * F_DIM + t0 + tx * 4;
#pragma unroll
            for (int j = 0; j < 4; j++)
                s[i][j] = mr[j] ? s[i][j] * scale : -10000.0f;
        }
        __syncthreads();  // everyone done reading Ks before overwriting with P

        // Online softmax (row reduction across the 16 tx lanes of each half-warp)
#pragma unroll
        for (int i = 0; i < 4; i++) {
            float mt = s[i][0];
#pragma unroll
            for (int j = 1; j < 4; j++) mt = fmaxf(mt, s[i][j]);
#pragma unroll
            for (int off = 1; off < 16; off <<= 1)
                mt = fmaxf(mt, __shfl_xor_sync(0xffffffffu, mt, off));
            float mnew = fmaxf(m_i[i], mt);
            float corr = __expf(m_i[i] - mnew);
            m_i[i] = mnew;
            float ps = 0.0f;
#pragma unroll
            for (int j = 0; j < 4; j++) {
                float p = __expf(s[i][j] - mnew);
                s[i][j] = p;
                ps += p;
            }
#pragma unroll
            for (int off = 1; off < 16; off <<= 1)
                ps += __shfl_xor_sync(0xffffffffu, ps, off);
            l_i[i] = l_i[i] * corr + ps;
#pragma unroll
            for (int k = 0; k < 4; k++) o[i][k] *= corr;
#pragma unroll
            for (int j = 0; j < 4; j++)
                Ks[(ty * 4 + i) * 65 + tx * 4 + j] = s[i][j];  // P tile
        }
        __syncthreads();

        // O += P @ V
#pragma unroll
        for (int j = 0; j < 64; j++) {
            float pv[4], vv[4];
#pragma unroll
            for (int i = 0; i < 4; i++) pv[i] = Ks[(ty * 4 + i) * 65 + j];
#pragma unroll
            for (int k = 0; k < 4; k++) vv[k] = Vs[j * 64 + tx * 4 + k];
#pragma unroll
            for (int i = 0; i < 4; i++)
#pragma unroll
                for (int k = 0; k < 4; k++) o[i][k] += pv[i] * vv[k];
        }
    }

    // ctx[f][b][n*64+e] = o / l
#pragma unroll
    for (int i = 0; i < 4; i++) {
        int fg = f0 + ty * 4 + i;
        float inv = 1.0f / l_i[i];
        float* cp = ctx + ((long long)fg * B_DIM + b) * H_DIM + n * E_DIM + tx * 4;
#pragma unroll
        for (int k = 0; k < 4; k++) cp[k] = o[i][k] * inv;
    }
}

// ---------------------------------------------------------------------------
// Launch
// ---------------------------------------------------------------------------
extern "C" void kernel_launch(void* const* d_in, const int* in_sizes, int n_in,
                              void* d_out, int out_size) {
    const float* q_input        = (const float*)d_in[0];
    const unsigned char* mask   = (const unsigned char*)d_in[1];
    const float* w_qkv          = (const float*)d_in[2];
    const float* b_qkv          = (const float*)d_in[3];
    const float* w_out          = (const float*)d_in[4];  // [N,E,H] == [1024,1024]
    const float* b_out          = (const float*)d_in[5];
    float* out                  = (float*)d_out;

    cudaFuncSetAttribute(attention_kernel,
                         cudaFuncAttributeMaxDynamicSharedMemorySize,
                         ATT_SMEM_BYTES);

    void* qkv_p = nullptr;
    void* ctx_p = nullptr;
    cudaGetSymbolAddress(&qkv_p, g_qkv);
    cudaGetSymbolAddress(&ctx_p, g_ctx);

    // 1) Canonicalize mask to u8
    detect_mask_kernel<<<1, 256>>>(mask);
    long long mask_elems = (long long)B_DIM * F_DIM * F_DIM;
    convert_mask_kernel<<<(unsigned)((mask_elems + 255) / 256), 256>>>(mask);

    // 2) QKV projection: [4096,1024] @ [1024,3072] + b_qkv
    dim3 g1(H3 / 128, FB / 128);
    sgemm_kernel<<<g1, 256>>>(q_input, w_qkv, b_qkv, (float*)qkv_p,
                              FB, H3, H_DIM);

    // 3) Fused attention -> ctx [F,B,H]
    dim3 ga(F_DIM / 64, N_HEADS, B_DIM);
    attention_kernel<<<ga, 256, ATT_SMEM_BYTES>>>((const float*)qkv_p,
                                                  (float*)ctx_p);

    // 4) Output projection: [4096,1024] @ [1024,1024] (no bias per reference)
    dim3 g2(H_DIM / 128, FB / 128);
    sgemm_kernel<<<g2, 256>>>((const float*)ctx_p, w_out, nullptr, out,
                              FB, H_DIM, H_DIM);

    // 5) Tuple tail: reference returns (out, b_out)
    long long main_elems = (long long)FB * H_DIM;
    if ((long long)out_size >= main_elems + H_DIM) {
        cudaMemcpyAsync(out + main_elems, b_out, H_DIM * sizeof(float),
                        cudaMemcpyDeviceToDevice);
    }
}